// round 5
// baseline (speedup 1.0000x reference)
#include <cuda_runtime.h>

// Closed form (derived R0): theta_i = x[b,i]+w[i], c_i = cos(2*theta_i)
//   out[b] = { c1*c2*c3, c0*c1, c0*c1*c2, c0*c1*c2*c3 }
//
// R5: perfect single wave — 1184 CTAs (8 per SM exactly, 148 SMs) x 256 thr
// = 303104 threads at 100% occupancy (64 warps/SM). Items per thread: 7 for
// tid < 278528, else 6 (warp-uniform). Rotating 4-deep load pipeline.
// Default writeback stores (R4's .cs forced DRAM writes every replay).

#define NTHREADS 256
#define NBLOCKS  1184
#define TSTRIDE  (NTHREADS * NBLOCKS)        // 303104
#define TOTAL    2097152                     // BATCH
#define SPLIT    (TOTAL - 6 * TSTRIDE)       // 278528: threads below do 7 items

__device__ __forceinline__ float4 proc(float4 xv, float w0, float w1,
                                       float w2, float w3)
{
    float c0 = __cosf(fmaf(2.0f, xv.x, w0));
    float c1 = __cosf(fmaf(2.0f, xv.y, w1));
    float c2 = __cosf(fmaf(2.0f, xv.z, w2));
    float c3 = __cosf(fmaf(2.0f, xv.w, w3));
    float t01  = c0 * c1;
    float t012 = t01 * c2;
    float4 o;
    o.x = c1 * c2 * c3;
    o.y = t01;
    o.z = t012;
    o.w = t012 * c3;
    return o;
}

__global__ void __launch_bounds__(NTHREADS, 8)
hilbert_fast(const float4* __restrict__ x4,
             const float* __restrict__ w,
             float4* __restrict__ out4)
{
    int tid = blockIdx.x * NTHREADS + threadIdx.x;
    bool has7 = (tid < SPLIT);

    float w0 = 2.0f * w[0], w1 = 2.0f * w[1];
    float w2 = 2.0f * w[2], w3 = 2.0f * w[3];

    // prologue: fill 4 pipeline slots (items 0..3 valid for all threads)
    float4 v0 = x4[tid + 0 * TSTRIDE];
    float4 v1 = x4[tid + 1 * TSTRIDE];
    float4 v2 = x4[tid + 2 * TSTRIDE];
    float4 v3 = x4[tid + 3 * TSTRIDE];

    // item 0: consume v0, refill slot0 with item 4
    float4 o0 = proc(v0, w0, w1, w2, w3);
    v0 = x4[tid + 4 * TSTRIDE];
    out4[tid + 0 * TSTRIDE] = o0;

    // item 1: consume v1, refill slot1 with item 5
    float4 o1 = proc(v1, w0, w1, w2, w3);
    v1 = x4[tid + 5 * TSTRIDE];
    out4[tid + 1 * TSTRIDE] = o1;

    // item 2: consume v2, refill slot2 with item 6 (only if this thread has 7)
    float4 o2 = proc(v2, w0, w1, w2, w3);
    if (has7) v2 = x4[tid + 6 * TSTRIDE];
    out4[tid + 2 * TSTRIDE] = o2;

    // items 3..5: consume remaining slots
    out4[tid + 3 * TSTRIDE] = proc(v3, w0, w1, w2, w3);
    out4[tid + 4 * TSTRIDE] = proc(v0, w0, w1, w2, w3);
    out4[tid + 5 * TSTRIDE] = proc(v1, w0, w1, w2, w3);

    // item 6 (tail, warp-uniform predicate)
    if (has7)
        out4[tid + 6 * TSTRIDE] = proc(v2, w0, w1, w2, w3);
}

// Generic fallback (any n of float4s).
__global__ void __launch_bounds__(256)
hilbert_generic(const float4* __restrict__ x4,
                const float* __restrict__ w,
                float4* __restrict__ out4, int n)
{
    int i = blockIdx.x * blockDim.x + threadIdx.x;
    if (i >= n) return;
    float w0 = 2.0f * w[0], w1 = 2.0f * w[1];
    float w2 = 2.0f * w[2], w3 = 2.0f * w[3];
    out4[i] = proc(x4[i], w0, w1, w2, w3);
}

extern "C" void kernel_launch(void* const* d_in, const int* in_sizes, int n_in,
                              void* d_out, int out_size)
{
    const float* x = (const float*)d_in[0];
    const float* w = (const float*)d_in[1];
    int nx = in_sizes[0];
    if (n_in >= 2 && in_sizes[0] < in_sizes[1]) {
        x = (const float*)d_in[1];
        w = (const float*)d_in[0];
        nx = in_sizes[1];
    }

    int n = nx / 4;  // float4 count (= batch)

    if (n == TOTAL) {
        hilbert_fast<<<NBLOCKS, NTHREADS>>>(
            (const float4*)x, w, (float4*)d_out);
    } else {
        int threads = 256;
        int blocks = (n + threads - 1) / threads;
        hilbert_generic<<<blocks, threads>>>(
            (const float4*)x, w, (float4*)d_out, n);
    }
}